// round 1
// baseline (speedup 1.0000x reference)
#include <cuda_runtime.h>
#include <cstddef>

// Problem constants
#define BATCH   2
#define NTOK    2048          // L*K = 512*4
#define DMODEL  1024
#define HEADS   16
#define HD      64
#define MROWS   (BATCH*NTOK)  // 4096

// ---------------- scratch (device globals; no allocation allowed) ----------
__device__ __align__(16) float g_hpe[MROWS * DMODEL];
__device__ __align__(16) float g_q  [MROWS * DMODEL];
__device__ __align__(16) float g_k  [MROWS * DMODEL];
__device__ __align__(16) float g_v  [MROWS * DMODEL];
__device__ __align__(16) float g_ctx[MROWS * DMODEL];
__device__ __align__(16) float g_pb [BATCH * NTOK];

// ---------------- hpe = h + sinusoidal PE ----------------------------------
__global__ void build_hpe_kernel(const float* __restrict__ h, float* __restrict__ hpe) {
    int idx = blockIdx.x * blockDim.x + threadIdx.x;        // float4 index
    // total float4s = MROWS * DMODEL / 4 = 1,048,576
    int row = idx >> 8;                 // 256 float4 per row of 1024
    int d   = (idx & 255) * 4;          // d multiple of 4
    int n   = row & (NTOK - 1);         // token index within batch

    const float c1 = -9.210340371976184f / 1024.0f;  // -ln(10000)/D
    float fn = (float)n;

    float div0 = expf((float)d * c1);          // pair (d, d+1): 2p = d
    float div1 = expf((float)(d + 2) * c1);    // pair (d+2, d+3)
    float s0, c0, s1, c1v;
    sincosf(fn * div0, &s0, &c0);
    sincosf(fn * div1, &s1, &c1v);

    float4 v = reinterpret_cast<const float4*>(h)[idx];
    v.x += s0; v.y += c0; v.z += s1; v.w += c1v;
    reinterpret_cast<float4*>(hpe)[idx] = v;
}

// ---------------- pbias[b,n] = scale * log(probs + 1e-8) -------------------
__global__ void build_pbias_kernel(const float* __restrict__ probs,
                                   const float* __restrict__ scale,
                                   float* __restrict__ pb) {
    int i = blockIdx.x * blockDim.x + threadIdx.x;
    if (i < BATCH * NTOK)
        pb[i] = scale[0] * logf(probs[i] + 1e-8f);
}

// ---------------- SGEMM: C[M,1024] = A[M,1024] @ W[1024,1024]^T + bias -----
// NT gemm: both A and W are row-major with K contiguous.
// Tile 128x128x16, 256 threads, 8x8 per thread.
__global__ __launch_bounds__(256, 2)
void gemm_nt_bias_kernel(const float* __restrict__ A, const float* __restrict__ W,
                         const float* __restrict__ bias, float* __restrict__ C) {
    __shared__ float As[16 * 128];   // As[k][m]
    __shared__ float Bs[16 * 128];   // Bs[k][n]

    const int tid = threadIdx.x;
    const int tx = tid & 15, ty = tid >> 4;
    const int bn = blockIdx.x;       // over N/128 = 8
    const int bm = blockIdx.y;       // over M/128 = 32

    const float* Ab = A + (size_t)(bm * 128) * DMODEL;
    const float* Wb = W + (size_t)(bn * 128) * DMODEL;

    float acc[8][8];
#pragma unroll
    for (int i = 0; i < 8; i++)
#pragma unroll
        for (int j = 0; j < 8; j++) acc[i][j] = 0.0f;

    for (int k0 = 0; k0 < DMODEL; k0 += 16) {
#pragma unroll
        for (int l = 0; l < 2; l++) {
            int f  = tid + l * 256;      // 0..511 float4s of 128x16 tile
            int r  = f >> 2;             // row 0..127
            int c4 = (f & 3) * 4;        // k within tile, multiple of 4
            float4 a = *reinterpret_cast<const float4*>(Ab + (size_t)r * DMODEL + k0 + c4);
            As[(c4 + 0) * 128 + r] = a.x;
            As[(c4 + 1) * 128 + r] = a.y;
            As[(c4 + 2) * 128 + r] = a.z;
            As[(c4 + 3) * 128 + r] = a.w;
            float4 w = *reinterpret_cast<const float4*>(Wb + (size_t)r * DMODEL + k0 + c4);
            Bs[(c4 + 0) * 128 + r] = w.x;
            Bs[(c4 + 1) * 128 + r] = w.y;
            Bs[(c4 + 2) * 128 + r] = w.z;
            Bs[(c4 + 3) * 128 + r] = w.w;
        }
        __syncthreads();

#pragma unroll
        for (int kk = 0; kk < 16; kk++) {
            float4 a0 = *reinterpret_cast<const float4*>(As + kk * 128 + ty * 8);
            float4 a1 = *reinterpret_cast<const float4*>(As + kk * 128 + ty * 8 + 4);
            float4 b0 = *reinterpret_cast<const float4*>(Bs + kk * 128 + tx * 8);
            float4 b1 = *reinterpret_cast<const float4*>(Bs + kk * 128 + tx * 8 + 4);
            float ar[8] = {a0.x, a0.y, a0.z, a0.w, a1.x, a1.y, a1.z, a1.w};
            float br[8] = {b0.x, b0.y, b0.z, b0.w, b1.x, b1.y, b1.z, b1.w};
#pragma unroll
            for (int i = 0; i < 8; i++)
#pragma unroll
                for (int j = 0; j < 8; j++)
                    acc[i][j] = fmaf(ar[i], br[j], acc[i][j]);
        }
        __syncthreads();
    }

    const int col0 = bn * 128 + tx * 8;
    const int row0 = bm * 128 + ty * 8;
    float br[8];
#pragma unroll
    for (int j = 0; j < 8; j++) br[j] = bias[col0 + j];
#pragma unroll
    for (int i = 0; i < 8; i++) {
        float4 r0 = make_float4(acc[i][0] + br[0], acc[i][1] + br[1],
                                acc[i][2] + br[2], acc[i][3] + br[3]);
        float4 r1 = make_float4(acc[i][4] + br[4], acc[i][5] + br[5],
                                acc[i][6] + br[6], acc[i][7] + br[7]);
        float* cp = C + (size_t)(row0 + i) * DMODEL + col0;
        *reinterpret_cast<float4*>(cp)     = r0;
        *reinterpret_cast<float4*>(cp + 4) = r1;
    }
}

// ---------------- Flash attention (fp32, online softmax, key bias) ---------
// Block: one (b, head, 64-row q tile). 256 threads = 16x16, 4x4 frags.
__global__ __launch_bounds__(256)
void flash_attn_kernel(const float* __restrict__ Q, const float* __restrict__ Km,
                       const float* __restrict__ Vm, const float* __restrict__ pbias,
                       float* __restrict__ ctx) {
    extern __shared__ float sm[];
    float* Qst = sm;             // [d][i]  64x64 transposed
    float* Kst = sm + 4096;      // [d][j]
    float* Vs  = sm + 8192;      // [j][d]
    float* Ps  = sm + 12288;     // [i][j]
    float* pbs = sm + 16384;     // [64]

    const int tid = threadIdx.x;
    const int tx = tid & 15, ty = tid >> 4;
    const int qt = blockIdx.x, hh = blockIdx.y, b = blockIdx.z;
    const float scale = 0.125f;  // 1/sqrt(64)

    const float* qb = Q + (size_t)(b * NTOK + qt * 64) * DMODEL + hh * HD;
#pragma unroll
    for (int l = 0; l < 4; l++) {
        int e = tid + l * 256;       // 0..1023 float4s
        int r = e >> 4;
        int d = (e & 15) * 4;
        float4 v = *reinterpret_cast<const float4*>(qb + (size_t)r * DMODEL + d);
        Qst[(d + 0) * 64 + r] = v.x;
        Qst[(d + 1) * 64 + r] = v.y;
        Qst[(d + 2) * 64 + r] = v.z;
        Qst[(d + 3) * 64 + r] = v.w;
    }

    float o[4][4];
    float mrow[4], lrow[4];
#pragma unroll
    for (int i = 0; i < 4; i++) {
        mrow[i] = -1e30f;
        lrow[i] = 0.0f;
#pragma unroll
        for (int d = 0; d < 4; d++) o[i][d] = 0.0f;
    }

    for (int kt = 0; kt < NTOK / 64; kt++) {
        const float* kb = Km + (size_t)(b * NTOK + kt * 64) * DMODEL + hh * HD;
        const float* vb = Vm + (size_t)(b * NTOK + kt * 64) * DMODEL + hh * HD;
#pragma unroll
        for (int l = 0; l < 4; l++) {
            int e = tid + l * 256;
            int r = e >> 4;
            int d = (e & 15) * 4;
            float4 kv = *reinterpret_cast<const float4*>(kb + (size_t)r * DMODEL + d);
            Kst[(d + 0) * 64 + r] = kv.x;
            Kst[(d + 1) * 64 + r] = kv.y;
            Kst[(d + 2) * 64 + r] = kv.z;
            Kst[(d + 3) * 64 + r] = kv.w;
            float4 vv = *reinterpret_cast<const float4*>(vb + (size_t)r * DMODEL + d);
            *reinterpret_cast<float4*>(Vs + r * 64 + d) = vv;
        }
        if (tid < 64) pbs[tid] = pbias[b * NTOK + kt * 64 + tid];
        __syncthreads();

        // S = Q K^T (64x64), 4x4 frag per thread
        float s[4][4];
#pragma unroll
        for (int i = 0; i < 4; i++)
#pragma unroll
            for (int j = 0; j < 4; j++) s[i][j] = 0.0f;

#pragma unroll
        for (int d = 0; d < 64; d++) {
            float4 a  = *reinterpret_cast<const float4*>(Qst + d * 64 + ty * 4);
            float4 bb = *reinterpret_cast<const float4*>(Kst + d * 64 + tx * 4);
            float ar[4] = {a.x, a.y, a.z, a.w};
            float br[4] = {bb.x, bb.y, bb.z, bb.w};
#pragma unroll
            for (int i = 0; i < 4; i++)
#pragma unroll
                for (int j = 0; j < 4; j++)
                    s[i][j] = fmaf(ar[i], br[j], s[i][j]);
        }

        float pbf[4];
#pragma unroll
        for (int j = 0; j < 4; j++) pbf[j] = pbs[tx * 4 + j];

#pragma unroll
        for (int i = 0; i < 4; i++) {
            float tmax = -1e30f;
#pragma unroll
            for (int j = 0; j < 4; j++) {
                s[i][j] = fmaf(s[i][j], scale, pbf[j]);
                tmax = fmaxf(tmax, s[i][j]);
            }
#pragma unroll
            for (int msk = 8; msk > 0; msk >>= 1)
                tmax = fmaxf(tmax, __shfl_xor_sync(0xffffffffu, tmax, msk));

            float mn = fmaxf(mrow[i], tmax);
            float corr = __expf(mrow[i] - mn);
            mrow[i] = mn;

            float rs = 0.0f;
#pragma unroll
            for (int j = 0; j < 4; j++) {
                float p = __expf(s[i][j] - mn);
                s[i][j] = p;
                rs += p;
            }
#pragma unroll
            for (int msk = 8; msk > 0; msk >>= 1)
                rs += __shfl_xor_sync(0xffffffffu, rs, msk);

            lrow[i] = lrow[i] * corr + rs;
#pragma unroll
            for (int d = 0; d < 4; d++) o[i][d] *= corr;
#pragma unroll
            for (int j = 0; j < 4; j++)
                Ps[(ty * 4 + i) * 64 + tx * 4 + j] = s[i][j];
        }
        __syncthreads();

        // O += P V
#pragma unroll
        for (int j = 0; j < 64; j++) {
            float4 vv = *reinterpret_cast<const float4*>(Vs + j * 64 + tx * 4);
            float vr[4] = {vv.x, vv.y, vv.z, vv.w};
            float p0 = Ps[(ty * 4 + 0) * 64 + j];
            float p1 = Ps[(ty * 4 + 1) * 64 + j];
            float p2 = Ps[(ty * 4 + 2) * 64 + j];
            float p3 = Ps[(ty * 4 + 3) * 64 + j];
#pragma unroll
            for (int d = 0; d < 4; d++) {
                o[0][d] = fmaf(p0, vr[d], o[0][d]);
                o[1][d] = fmaf(p1, vr[d], o[1][d]);
                o[2][d] = fmaf(p2, vr[d], o[2][d]);
                o[3][d] = fmaf(p3, vr[d], o[3][d]);
            }
        }
        __syncthreads();
    }

    float* ob = ctx + (size_t)(b * NTOK + qt * 64 + ty * 4) * DMODEL + hh * HD + tx * 4;
#pragma unroll
    for (int i = 0; i < 4; i++) {
        float inv = 1.0f / lrow[i];
        float4 r = make_float4(o[i][0] * inv, o[i][1] * inv, o[i][2] * inv, o[i][3] * inv);
        *reinterpret_cast<float4*>(ob + (size_t)i * DMODEL) = r;
    }
}

// ---------------- launch ----------------------------------------------------
extern "C" void kernel_launch(void* const* d_in, const int* in_sizes, int n_in,
                              void* d_out, int out_size) {
    const float* h     = (const float*)d_in[0];
    const float* probs = (const float*)d_in[1];
    const float* Wq    = (const float*)d_in[2];
    const float* bq    = (const float*)d_in[3];
    const float* Wk    = (const float*)d_in[4];
    const float* bk    = (const float*)d_in[5];
    const float* Wv    = (const float*)d_in[6];
    const float* bv    = (const float*)d_in[7];
    const float* Wo    = (const float*)d_in[8];
    const float* bo    = (const float*)d_in[9];
    const float* pscal = (const float*)d_in[10];
    float* out = (float*)d_out;

    float *hpe, *q, *k, *v, *ctx, *pb;
    cudaGetSymbolAddress((void**)&hpe, g_hpe);
    cudaGetSymbolAddress((void**)&q,   g_q);
    cudaGetSymbolAddress((void**)&k,   g_k);
    cudaGetSymbolAddress((void**)&v,   g_v);
    cudaGetSymbolAddress((void**)&ctx, g_ctx);
    cudaGetSymbolAddress((void**)&pb,  g_pb);

    // 1. hpe = h + PE
    build_hpe_kernel<<<MROWS * DMODEL / 4 / 256, 256>>>(h, hpe);

    // 2. pbias
    build_pbias_kernel<<<(BATCH * NTOK + 255) / 256, 256>>>(probs, pscal, pb);

    // 3. Q/K/V projections
    dim3 ggrid(DMODEL / 128, MROWS / 128);
    gemm_nt_bias_kernel<<<ggrid, 256>>>(hpe, Wq, bq, q);
    gemm_nt_bias_kernel<<<ggrid, 256>>>(hpe, Wk, bk, k);
    gemm_nt_bias_kernel<<<ggrid, 256>>>(hpe, Wv, bv, v);

    // 4. flash attention
    size_t smem = (4 * 4096 + 64) * sizeof(float);  // 65,792 B
    cudaFuncSetAttribute(flash_attn_kernel,
                         cudaFuncAttributeMaxDynamicSharedMemorySize, (int)smem);
    dim3 fgrid(NTOK / 64, HEADS, BATCH);
    flash_attn_kernel<<<fgrid, 256, smem>>>(q, k, v, pb, ctx);

    // 5. output projection -> d_out
    gemm_nt_bias_kernel<<<ggrid, 256>>>(ctx, Wo, bo, out);
}

// round 3
// speedup vs baseline: 2.6953x; 2.6953x over previous
#include <cuda_runtime.h>
#include <cuda_bf16.h>
#include <cstdint>
#include <cstddef>

#define BATCH   2
#define NTOK    2048
#define DMODEL  1024
#define HEADS   16
#define HD      64
#define MROWS   (BATCH*NTOK)  // 4096

// ======================= helpers ============================================
__device__ __forceinline__ uint32_t smem_u32(const void* p) {
    uint32_t a;
    asm("{ .reg .u64 t; cvta.to.shared.u64 t, %1; cvt.u32.u64 %0, t; }" : "=r"(a) : "l"(p));
    return a;
}
__device__ __forceinline__ void ldsm_x4(uint32_t r[4], uint32_t a) {
    asm volatile("ldmatrix.sync.aligned.m8n8.x4.shared.b16 {%0,%1,%2,%3}, [%4];"
        : "=r"(r[0]), "=r"(r[1]), "=r"(r[2]), "=r"(r[3]) : "r"(a));
}
__device__ __forceinline__ void ldsm_x4t(uint32_t r[4], uint32_t a) {
    asm volatile("ldmatrix.sync.aligned.m8n8.x4.trans.shared.b16 {%0,%1,%2,%3}, [%4];"
        : "=r"(r[0]), "=r"(r[1]), "=r"(r[2]), "=r"(r[3]) : "r"(a));
}
__device__ __forceinline__ void mma_bf16(float* c, const uint32_t* a, uint32_t b0, uint32_t b1) {
    asm volatile("mma.sync.aligned.m16n8k16.row.col.f32.bf16.bf16.f32 "
        "{%0,%1,%2,%3}, {%4,%5,%6,%7}, {%8,%9}, {%0,%1,%2,%3};"
        : "+f"(c[0]), "+f"(c[1]), "+f"(c[2]), "+f"(c[3])
        : "r"(a[0]), "r"(a[1]), "r"(a[2]), "r"(a[3]), "r"(b0), "r"(b1));
}
__device__ __forceinline__ ushort bfhi(float x) {
    return __bfloat16_as_ushort(__float2bfloat16(x));
}
// pack two floats into (hi-part bf16x2, lo-residual bf16x2); element a in low half
__device__ __forceinline__ void split2(float a, float b, uint32_t& hi, uint32_t& lo) {
    ushort ah = bfhi(a), bh = bfhi(b);
    float ar = a - __bfloat162float(__ushort_as_bfloat16(ah));
    float br = b - __bfloat162float(__ushort_as_bfloat16(bh));
    hi = (uint32_t)ah | ((uint32_t)bfhi(b) << 16);
    hi = (uint32_t)ah | ((uint32_t)bh << 16);
    lo = (uint32_t)bfhi(ar) | ((uint32_t)bfhi(br) << 16);
}

// ======================= scratch (device globals) ===========================
__device__ __align__(16) __nv_bfloat16 g_hpe_hi[MROWS * DMODEL];
__device__ __align__(16) __nv_bfloat16 g_hpe_lo[MROWS * DMODEL];
__device__ __align__(16) __nv_bfloat16 g_w_hi[4 * DMODEL * DMODEL];
__device__ __align__(16) __nv_bfloat16 g_w_lo[4 * DMODEL * DMODEL];
__device__ __align__(16) __nv_bfloat16 g_qh[MROWS * DMODEL];
__device__ __align__(16) __nv_bfloat16 g_ql[MROWS * DMODEL];
__device__ __align__(16) __nv_bfloat16 g_kh[MROWS * DMODEL];
__device__ __align__(16) __nv_bfloat16 g_kl[MROWS * DMODEL];
__device__ __align__(16) __nv_bfloat16 g_vh[MROWS * DMODEL];
__device__ __align__(16) __nv_bfloat16 g_vl[MROWS * DMODEL];
__device__ __align__(16) __nv_bfloat16 g_ctx_hi[MROWS * DMODEL];
__device__ __align__(16) __nv_bfloat16 g_ctx_lo[MROWS * DMODEL];
__device__ __align__(16) float g_pb[BATCH * NTOK];

// ======================= prep kernels =======================================
__global__ void build_hpe_split_kernel(const float* __restrict__ h,
                                       __nv_bfloat16* __restrict__ hi,
                                       __nv_bfloat16* __restrict__ lo) {
    int idx = blockIdx.x * blockDim.x + threadIdx.x;   // float4 index
    int row = idx >> 8;
    int d   = (idx & 255) * 4;
    int n   = row & (NTOK - 1);
    const float c1 = -9.210340371976184f / 1024.0f;
    float fn = (float)n;
    float div0 = expf((float)d * c1);
    float div1 = expf((float)(d + 2) * c1);
    float s0, c0, s1, c1v;
    sincosf(fn * div0, &s0, &c0);
    sincosf(fn * div1, &s1, &c1v);
    float4 v = reinterpret_cast<const float4*>(h)[idx];
    float x0 = v.x + s0, x1 = v.y + c0, x2 = v.z + s1, x3 = v.w + c1v;
    uint32_t h01, l01, h23, l23;
    split2(x0, x1, h01, l01);
    split2(x2, x3, h23, l23);
    reinterpret_cast<uint2*>(hi)[idx] = make_uint2(h01, h23);
    reinterpret_cast<uint2*>(lo)[idx] = make_uint2(l01, l23);
}

__global__ void split_weights_kernel(const float* __restrict__ Wq, const float* __restrict__ Wk,
                                     const float* __restrict__ Wv, const float* __restrict__ Wo,
                                     __nv_bfloat16* __restrict__ hi, __nv_bfloat16* __restrict__ lo) {
    int m = blockIdx.y;
    const float* src = (m == 0) ? Wq : (m == 1) ? Wk : (m == 2) ? Wv : Wo;
    int idx = blockIdx.x * blockDim.x + threadIdx.x;
    float4 v = reinterpret_cast<const float4*>(src)[idx];
    uint32_t h01, l01, h23, l23;
    split2(v.x, v.y, h01, l01);
    split2(v.z, v.w, h23, l23);
    size_t base = (size_t)m * (DMODEL * DMODEL / 4);
    reinterpret_cast<uint2*>(hi)[base + idx] = make_uint2(h01, h23);
    reinterpret_cast<uint2*>(lo)[base + idx] = make_uint2(l01, l23);
}

__global__ void build_pbias_kernel(const float* __restrict__ probs,
                                   const float* __restrict__ scale,
                                   float* __restrict__ pb) {
    int i = blockIdx.x * blockDim.x + threadIdx.x;
    if (i < BATCH * NTOK)
        pb[i] = scale[0] * logf(probs[i] + 1e-8f);
}

// ================= HMMA split-bf16 GEMM =====================================
// C[4096,1024] = A @ W^T + bias. Tile 128x128, K-chunk 64, 256 thr (8 warps).
// smem pitch: 72 bf16 (144B) per row -> conflict-free ldmatrix.
#define GPB 144
#define GEMM_SMEM (4 * 128 * GPB)   // 73728

__global__ __launch_bounds__(256)
void gemm_mma_kernel(const __nv_bfloat16* __restrict__ Ahi, const __nv_bfloat16* __restrict__ Alo,
                     const __nv_bfloat16* __restrict__ Bhi, const __nv_bfloat16* __restrict__ Blo,
                     const float* __restrict__ bias,
                     float* __restrict__ Cf,
                     __nv_bfloat16* __restrict__ Chi, __nv_bfloat16* __restrict__ Clo) {
    extern __shared__ __align__(16) char sm[];
    char* sAh = sm;
    char* sAl = sm + 18432;
    char* sBh = sm + 36864;
    char* sBl = sm + 55296;
    const uint32_t sb = smem_u32(sm);

    const int tid = threadIdx.x, lane = tid & 31, wid = tid >> 5;
    const int wm = wid & 3, wn = wid >> 2;
    const int m0 = blockIdx.y * 128, n0 = blockIdx.x * 128;

    const uint4* A4h = (const uint4*)Ahi;
    const uint4* A4l = (const uint4*)Alo;
    const uint4* B4h = (const uint4*)Bhi;
    const uint4* B4l = (const uint4*)Blo;

    float acc[2][8][4];
#pragma unroll
    for (int mi = 0; mi < 2; mi++)
#pragma unroll
        for (int nj = 0; nj < 8; nj++)
#pragma unroll
            for (int q = 0; q < 4; q++) acc[mi][nj][q] = 0.0f;

    const int lr = (lane & 7) + ((lane >> 3) & 1) * 8;
    const int lk = (lane >> 4) * 8;

    for (int kc = 0; kc < 16; kc++) {
        if (kc) __syncthreads();
#pragma unroll
        for (int t = 0; t < 4; t++) {
            int u = tid + t * 256;
            int r = u >> 3, s = u & 7;
            int gi = (m0 + r) * 128 + kc * 8 + s;
            *(uint4*)(sAh + r * GPB + s * 16) = A4h[gi];
            *(uint4*)(sAl + r * GPB + s * 16) = A4l[gi];
            int gj = (n0 + r) * 128 + kc * 8 + s;
            *(uint4*)(sBh + r * GPB + s * 16) = B4h[gj];
            *(uint4*)(sBl + r * GPB + s * 16) = B4l[gj];
        }
        __syncthreads();

#pragma unroll
        for (int ks = 0; ks < 4; ks++) {
            uint32_t ah[2][4], al[2][4];
#pragma unroll
            for (int mi = 0; mi < 2; mi++) {
                uint32_t off = (uint32_t)(wm * 32 + mi * 16 + lr) * GPB + (ks * 16 + lk) * 2;
                ldsm_x4(ah[mi], sb + off);
                ldsm_x4(al[mi], sb + 18432u + off);
            }
#pragma unroll
            for (int np = 0; np < 4; np++) {
                uint32_t off = (uint32_t)(wn * 64 + np * 16 + lr) * GPB + (ks * 16 + lk) * 2;
                uint32_t bh[4], bl[4];
                ldsm_x4(bh, sb + 36864u + off);
                ldsm_x4(bl, sb + 55296u + off);
#pragma unroll
                for (int mi = 0; mi < 2; mi++) {
                    mma_bf16(acc[mi][2 * np],     ah[mi], bh[0], bh[2]);
                    mma_bf16(acc[mi][2 * np + 1], ah[mi], bh[1], bh[3]);
                    mma_bf16(acc[mi][2 * np],     ah[mi], bl[0], bl[2]);
                    mma_bf16(acc[mi][2 * np + 1], ah[mi], bl[1], bl[3]);
                    mma_bf16(acc[mi][2 * np],     al[mi], bh[0], bh[2]);
                    mma_bf16(acc[mi][2 * np + 1], al[mi], bh[1], bh[3]);
                }
            }
        }
    }

    // epilogue
#pragma unroll
    for (int mi = 0; mi < 2; mi++) {
        int row = m0 + wm * 32 + mi * 16 + (lane >> 2);
#pragma unroll
        for (int nj = 0; nj < 8; nj++) {
            int col = n0 + wn * 64 + nj * 8 + (lane & 3) * 2;
            float b0 = bias[col], b1 = bias[col + 1];
            float v00 = acc[mi][nj][0] + b0, v01 = acc[mi][nj][1] + b1;
            float v10 = acc[mi][nj][2] + b0, v11 = acc[mi][nj][3] + b1;
            if (Cf) {
                *(float2*)(Cf + (size_t)row * DMODEL + col)       = make_float2(v00, v01);
                *(float2*)(Cf + (size_t)(row + 8) * DMODEL + col) = make_float2(v10, v11);
            } else {
                uint32_t hh, ll;
                split2(v00, v01, hh, ll);
                *(uint32_t*)(Chi + (size_t)row * DMODEL + col) = hh;
                *(uint32_t*)(Clo + (size_t)row * DMODEL + col) = ll;
                split2(v10, v11, hh, ll);
                *(uint32_t*)(Chi + (size_t)(row + 8) * DMODEL + col) = hh;
                *(uint32_t*)(Clo + (size_t)(row + 8) * DMODEL + col) = ll;
            }
        }
    }
}

// ================= HMMA flash attention =====================================
// Block: (b, head, 64 q-rows). 128 threads (4 warps), warp owns 16 rows.
// K-tile 64 per iter. All operands bf16 hi/lo split, fp32 accum.
// smem: Qh 0, Ql 9216, Kh 18432, Kl 27648, Vh 36864, Vl 46080, pb 55296
#define FL_SMEM (55296 + 256)

__global__ __launch_bounds__(128)
void flash_mma_kernel(const __nv_bfloat16* __restrict__ Qh, const __nv_bfloat16* __restrict__ Ql,
                      const __nv_bfloat16* __restrict__ Kh, const __nv_bfloat16* __restrict__ Kl,
                      const __nv_bfloat16* __restrict__ Vh, const __nv_bfloat16* __restrict__ Vl,
                      const float* __restrict__ pb,
                      __nv_bfloat16* __restrict__ Ch, __nv_bfloat16* __restrict__ Cl) {
    extern __shared__ __align__(16) char sm[];
    const uint32_t sb = smem_u32(sm);
    const int tid = threadIdx.x, lane = tid & 31, wid = tid >> 5;
    const int qt = blockIdx.x, hh = blockIdx.y, b = blockIdx.z;
    const int rq0 = b * NTOK + qt * 64;

    const uint4* Q4h = (const uint4*)Qh;
    const uint4* Q4l = (const uint4*)Ql;
    const uint4* K4h = (const uint4*)Kh;
    const uint4* K4l = (const uint4*)Kl;
    const uint4* V4h = (const uint4*)Vh;
    const uint4* V4l = (const uint4*)Vl;

    // load Q tile (64 x 64) hi/lo
#pragma unroll
    for (int t = 0; t < 4; t++) {
        int u = tid + t * 128;
        int r = u >> 3, s = u & 7;
        int gi = (rq0 + r) * 128 + hh * 8 + s;
        *(uint4*)(sm + 0    + r * GPB + s * 16) = Q4h[gi];
        *(uint4*)(sm + 9216 + r * GPB + s * 16) = Q4l[gi];
    }
    __syncthreads();

    const int lr = (lane & 7) + ((lane >> 3) & 1) * 8;
    const int lk = (lane >> 4) * 8;

    uint32_t qh[4][4], ql[4][4];
#pragma unroll
    for (int ks = 0; ks < 4; ks++) {
        uint32_t off = (uint32_t)(wid * 16 + lr) * GPB + (ks * 16 + lk) * 2;
        ldsm_x4(qh[ks], sb + off);
        ldsm_x4(ql[ks], sb + 9216u + off);
    }

    float o[8][4];
#pragma unroll
    for (int j = 0; j < 8; j++)
#pragma unroll
        for (int q = 0; q < 4; q++) o[j][q] = 0.0f;
    float mst0 = -1e30f, mst1 = -1e30f, lst0 = 0.0f, lst1 = 0.0f;

    for (int kt = 0; kt < NTOK / 64; kt++) {
        __syncthreads();
        int rk0 = b * NTOK + kt * 64;
#pragma unroll
        for (int t = 0; t < 4; t++) {
            int u = tid + t * 128;
            int r = u >> 3, s = u & 7;
            int gi = (rk0 + r) * 128 + hh * 8 + s;
            *(uint4*)(sm + 18432 + r * GPB + s * 16) = K4h[gi];
            *(uint4*)(sm + 27648 + r * GPB + s * 16) = K4l[gi];
            *(uint4*)(sm + 36864 + r * GPB + s * 16) = V4h[gi];
            *(uint4*)(sm + 46080 + r * GPB + s * 16) = V4l[gi];
        }
        if (tid < 64) ((float*)(sm + 55296))[tid] = pb[rk0 + tid];
        __syncthreads();

        // S = Q K^T (3-pass split)
        float s[8][4];
#pragma unroll
        for (int j = 0; j < 8; j++)
#pragma unroll
            for (int q = 0; q < 4; q++) s[j][q] = 0.0f;

#pragma unroll
        for (int ks = 0; ks < 4; ks++) {
#pragma unroll
            for (int np = 0; np < 4; np++) {
                uint32_t off = (uint32_t)(np * 16 + lr) * GPB + (ks * 16 + lk) * 2;
                uint32_t bh[4], bl[4];
                ldsm_x4(bh, sb + 18432u + off);
                ldsm_x4(bl, sb + 27648u + off);
                mma_bf16(s[2 * np],     qh[ks], bh[0], bh[2]);
                mma_bf16(s[2 * np + 1], qh[ks], bh[1], bh[3]);
                mma_bf16(s[2 * np],     qh[ks], bl[0], bl[2]);
                mma_bf16(s[2 * np + 1], qh[ks], bl[1], bl[3]);
                mma_bf16(s[2 * np],     ql[ks], bh[0], bh[2]);
                mma_bf16(s[2 * np + 1], ql[ks], bh[1], bh[3]);
            }
        }

        // softmax (rows: r0 = lane>>2, r1 = r0+8)
        float mx0 = -1e30f, mx1 = -1e30f;
        const float* pbs = (const float*)(sm + 55296);
#pragma unroll
        for (int j = 0; j < 8; j++) {
            int c = j * 8 + (lane & 3) * 2;
            float p0 = pbs[c], p1 = pbs[c + 1];
            s[j][0] = fmaf(s[j][0], 0.125f, p0);
            s[j][1] = fmaf(s[j][1], 0.125f, p1);
            s[j][2] = fmaf(s[j][2], 0.125f, p0);
            s[j][3] = fmaf(s[j][3], 0.125f, p1);
            mx0 = fmaxf(mx0, fmaxf(s[j][0], s[j][1]));
            mx1 = fmaxf(mx1, fmaxf(s[j][2], s[j][3]));
        }
        mx0 = fmaxf(mx0, __shfl_xor_sync(0xffffffffu, mx0, 1));
        mx0 = fmaxf(mx0, __shfl_xor_sync(0xffffffffu, mx0, 2));
        mx1 = fmaxf(mx1, __shfl_xor_sync(0xffffffffu, mx1, 1));
        mx1 = fmaxf(mx1, __shfl_xor_sync(0xffffffffu, mx1, 2));

        float mn0 = fmaxf(mst0, mx0), mn1 = fmaxf(mst1, mx1);
        float corr0 = __expf(mst0 - mn0), corr1 = __expf(mst1 - mn1);
        mst0 = mn0; mst1 = mn1;

        float sum0 = 0.0f, sum1 = 0.0f;
        uint32_t aph[4][4], apl[4][4];
#pragma unroll
        for (int j = 0; j < 8; j++) {
            float p0 = __expf(s[j][0] - mn0), p1 = __expf(s[j][1] - mn0);
            float p2 = __expf(s[j][2] - mn1), p3 = __expf(s[j][3] - mn1);
            sum0 += p0 + p1; sum1 += p2 + p3;
            uint32_t h01, l01, h23, l23;
            split2(p0, p1, h01, l01);
            split2(p2, p3, h23, l23);
            int ks = j >> 1, rb = (j & 1) * 2;
            aph[ks][rb] = h01; aph[ks][rb + 1] = h23;
            apl[ks][rb] = l01; apl[ks][rb + 1] = l23;
        }
        sum0 += __shfl_xor_sync(0xffffffffu, sum0, 1);
        sum0 += __shfl_xor_sync(0xffffffffu, sum0, 2);
        sum1 += __shfl_xor_sync(0xffffffffu, sum1, 1);
        sum1 += __shfl_xor_sync(0xffffffffu, sum1, 2);
        lst0 = lst0 * corr0 + sum0;
        lst1 = lst1 * corr1 + sum1;
#pragma unroll
        for (int j = 0; j < 8; j++) {
            o[j][0] *= corr0; o[j][1] *= corr0;
            o[j][2] *= corr1; o[j][3] *= corr1;
        }

        // O += P V (3-pass split); V via ldmatrix.trans
#pragma unroll
        for (int ks = 0; ks < 4; ks++) {
#pragma unroll
            for (int np = 0; np < 4; np++) {
                uint32_t off = (uint32_t)(ks * 16 + lr) * GPB + (np * 16 + lk) * 2;
                uint32_t vh[4], vl[4];
                ldsm_x4t(vh, sb + 36864u + off);
                ldsm_x4t(vl, sb + 46080u + off);
                mma_bf16(o[2 * np],     aph[ks], vh[0], vh[1]);
                mma_bf16(o[2 * np + 1], aph[ks], vh[2], vh[3]);
                mma_bf16(o[2 * np],     aph[ks], vl[0], vl[1]);
                mma_bf16(o[2 * np + 1], aph[ks], vl[2], vl[3]);
                mma_bf16(o[2 * np],     apl[ks], vh[0], vh[1]);
                mma_bf16(o[2 * np + 1], apl[ks], vh[2], vh[3]);
            }
        }
    }

    // epilogue: ctx = O / l, written as bf16 hi/lo
    float inv0 = 1.0f / lst0, inv1 = 1.0f / lst1;
    int row = rq0 + wid * 16 + (lane >> 2);
#pragma unroll
    for (int j = 0; j < 8; j++) {
        int col = hh * HD + j * 8 + (lane & 3) * 2;
        uint32_t hv, lv;
        split2(o[j][0] * inv0, o[j][1] * inv0, hv, lv);
        *(uint32_t*)(Ch + (size_t)row * DMODEL + col) = hv;
        *(uint32_t*)(Cl + (size_t)row * DMODEL + col) = lv;
        split2(o[j][2] * inv1, o[j][3] * inv1, hv, lv);
        *(uint32_t*)(Ch + (size_t)(row + 8) * DMODEL + col) = hv;
        *(uint32_t*)(Cl + (size_t)(row + 8) * DMODEL + col) = lv;
    }
}

// ---------------- launch ----------------------------------------------------
extern "C" void kernel_launch(void* const* d_in, const int* in_sizes, int n_in,
                              void* d_out, int out_size) {
    const float* h     = (const float*)d_in[0];
    const float* probs = (const float*)d_in[1];
    const float* Wq    = (const float*)d_in[2];
    const float* bq    = (const float*)d_in[3];
    const float* Wk    = (const float*)d_in[4];
    const float* bk    = (const float*)d_in[5];
    const float* Wv    = (const float*)d_in[6];
    const float* bv    = (const float*)d_in[7];
    const float* Wo    = (const float*)d_in[8];
    const float* bo    = (const float*)d_in[9];
    const float* pscal = (const float*)d_in[10];
    float* out = (float*)d_out;

    __nv_bfloat16 *hpeh, *hpel, *wh, *wl, *qh, *ql, *kh, *kl, *vh, *vl, *ctxh, *ctxl;
    float* pb;
    cudaGetSymbolAddress((void**)&hpeh, g_hpe_hi);
    cudaGetSymbolAddress((void**)&hpel, g_hpe_lo);
    cudaGetSymbolAddress((void**)&wh,   g_w_hi);
    cudaGetSymbolAddress((void**)&wl,   g_w_lo);
    cudaGetSymbolAddress((void**)&qh,   g_qh);
    cudaGetSymbolAddress((void**)&ql,   g_ql);
    cudaGetSymbolAddress((void**)&kh,   g_kh);
    cudaGetSymbolAddress((void**)&kl,   g_kl);
    cudaGetSymbolAddress((void**)&vh,   g_vh);
    cudaGetSymbolAddress((void**)&vl,   g_vl);
    cudaGetSymbolAddress((void**)&ctxh, g_ctx_hi);
    cudaGetSymbolAddress((void**)&ctxl, g_ctx_lo);
    cudaGetSymbolAddress((void**)&pb,   g_pb);

    cudaFuncSetAttribute(gemm_mma_kernel,
                         cudaFuncAttributeMaxDynamicSharedMemorySize, GEMM_SMEM);
    cudaFuncSetAttribute(flash_mma_kernel,
                         cudaFuncAttributeMaxDynamicSharedMemorySize, FL_SMEM);

    // prep
    build_hpe_split_kernel<<<MROWS * DMODEL / 4 / 256, 256>>>(h, hpeh, hpel);
    split_weights_kernel<<<dim3(DMODEL * DMODEL / 4 / 256, 4), 256>>>(Wq, Wk, Wv, Wo, wh, wl);
    build_pbias_kernel<<<(BATCH * NTOK + 255) / 256, 256>>>(probs, pscal, pb);

    // projections (epilogue writes bf16 hi/lo directly)
    const size_t WSZ = (size_t)DMODEL * DMODEL;
    dim3 ggrid(DMODEL / 128, MROWS / 128);   // (8, 32)
    gemm_mma_kernel<<<ggrid, 256, GEMM_SMEM>>>(hpeh, hpel, wh + 0 * WSZ, wl + 0 * WSZ, bq,
                                               nullptr, qh, ql);
    gemm_mma_kernel<<<ggrid, 256, GEMM_SMEM>>>(hpeh, hpel, wh + 1 * WSZ, wl + 1 * WSZ, bk,
                                               nullptr, kh, kl);
    gemm_mma_kernel<<<ggrid, 256, GEMM_SMEM>>>(hpeh, hpel, wh + 2 * WSZ, wl + 2 * WSZ, bv,
                                               nullptr, vh, vl);

    // flash attention
    dim3 fgrid(NTOK / 64, HEADS, BATCH);
    flash_mma_kernel<<<fgrid, 128, FL_SMEM>>>(qh, ql, kh, kl, vh, vl, pb, ctxh, ctxl);

    // output projection -> d_out (fp32)
    gemm_mma_kernel<<<ggrid, 256, GEMM_SMEM>>>(ctxh, ctxl, wh + 3 * WSZ, wl + 3 * WSZ, bo,
                                               out, nullptr, nullptr);
}